// round 7
// baseline (speedup 1.0000x reference)
#include <cuda_runtime.h>
#include <math.h>

#define Bb   8
#define LEAF 1024
#define Nn   2048
#define Dd   128
#define BN   (Bb * Nn)      // 16384
#define SFLAG 0x10000       // slist entry flag: row comes from g_Stop

// Scratch (allocation-free rule: device globals)
__device__ float g_nf  [BN * Dd];          // raw node features (tree means)
__device__ float g_h   [BN * Dd];          // gelu(LN(x))
__device__ float g_agg [BN * Dd];          // mean aggregation
__device__ float g_S7  [Bb * 128 * Dd];    // raw subtree sums S(128..255) per batch
__device__ float g_Stop[Bb * 32 * Dd];     // raw subtree sums S(32..63) per batch

// ---------------------------------------------------------------------------
// f32x2 packed helpers (SASS FFMA2 — PTX-only)
// ---------------------------------------------------------------------------
__device__ __forceinline__ unsigned long long pack2(float lo, float hi) {
    unsigned long long r;
    asm("mov.b64 %0, {%1, %2};" : "=l"(r) : "f"(lo), "f"(hi));
    return r;
}
__device__ __forceinline__ void unpack2(unsigned long long v, float& lo, float& hi) {
    asm("mov.b64 {%0, %1}, %2;" : "=f"(lo), "=f"(hi) : "l"(v));
}
__device__ __forceinline__ void ffma2(unsigned long long& d,
                                      unsigned long long a,
                                      unsigned long long b) {
    asm("fma.rn.f32x2 %0, %1, %2, %0;" : "+l"(d) : "l"(a), "l"(b));
}

// ---------------------------------------------------------------------------
// Tree build: pairwise mean up-sweep. Each thread owns one feature dim d.
// ---------------------------------------------------------------------------
__device__ __forceinline__ void reduce_store(const float v32[32], int bN, int base, int off, int d) {
    float v16[16];
#pragma unroll
    for (int j = 0; j < 16; j++) {
        v16[j] = 0.5f * (v32[2*j] + v32[2*j+1]);
        g_nf[(bN + (base >> 1) + (off >> 1) + j) * Dd + d] = v16[j];
    }
    float v8[8];
#pragma unroll
    for (int j = 0; j < 8; j++) {
        v8[j] = 0.5f * (v16[2*j] + v16[2*j+1]);
        g_nf[(bN + (base >> 2) + (off >> 2) + j) * Dd + d] = v8[j];
    }
    float v4[4];
#pragma unroll
    for (int j = 0; j < 4; j++) {
        v4[j] = 0.5f * (v8[2*j] + v8[2*j+1]);
        g_nf[(bN + (base >> 3) + (off >> 3) + j) * Dd + d] = v4[j];
    }
    float v2[2];
#pragma unroll
    for (int j = 0; j < 2; j++) {
        v2[j] = 0.5f * (v4[2*j] + v4[2*j+1]);
        g_nf[(bN + (base >> 4) + (off >> 4) + j) * Dd + d] = v2[j];
    }
    float v1 = 0.5f * (v2[0] + v2[1]);
    g_nf[(bN + (base >> 5) + (off >> 5)) * Dd + d] = v1;
}

__global__ void tree1_kernel(const float* __restrict__ elements) {
    int b = blockIdx.x >> 5;
    int s = blockIdx.x & 31;
    int d = threadIdx.x;
    int bN = b * Nn;
    float v32[32];
#pragma unroll
    for (int j = 0; j < 32; j++) {
        float v = elements[(b * LEAF + s * 32 + j) * Dd + d];
        v32[j] = v;
        g_nf[(bN + LEAF + s * 32 + j) * Dd + d] = v;
    }
    reduce_store(v32, bN, 1024, s * 32, d);
}

__global__ void tree2_kernel() {
    int b = blockIdx.x;
    int d = threadIdx.x;
    int bN = b * Nn;
    float v32[32];
#pragma unroll
    for (int j = 0; j < 32; j++)
        v32[j] = g_nf[(bN + 32 + j) * Dd + d];
    reduce_store(v32, bN, 32, 0, d);
    g_nf[bN * Dd + d] = -1.0f;  // global node 0
}

// ---------------------------------------------------------------------------
// x = nf + positional encoding; fused LN + exact GELU -> g_h (layer 0 input)
// ---------------------------------------------------------------------------
__global__ void encx_kernel(float* __restrict__ x,
                            const float* __restrict__ gamma,
                            const float* __restrict__ beta) {
    int gi = blockIdx.x;
    int node = gi & (Nn - 1);
    int d = threadIdx.x;
    float pos;
    if (node == 0) {
        pos = (d < 64) ? -0.5f : -1.0f;
    } else {
        int vp = 31 - __clz(node);
        pos = (d < 64) ? (float)(node - (1 << vp)) : (float)vp;
    }
    int dd = d & 63;
    int k = dd >> 1;
    float inv = expf(-0.28782313662425574f * (float)k);   // exp(-k*ln(1e4)/32)
    float ang = pos * inv;
    float e = (dd & 1) ? cosf(ang) : sinf(ang);
    float v = g_nf[gi * Dd + d] + e;
    x[gi * Dd + d] = v;

    float s = v, s2 = v * v;
#pragma unroll
    for (int o = 16; o; o >>= 1) {
        s  += __shfl_xor_sync(0xffffffffu, s, o);
        s2 += __shfl_xor_sync(0xffffffffu, s2, o);
    }
    __shared__ float ss[4], ss2[4];
    int w = d >> 5, lane = d & 31;
    if (lane == 0) { ss[w] = s; ss2[w] = s2; }
    __syncthreads();
    s  = ss[0] + ss[1] + ss[2] + ss[3];
    s2 = ss2[0] + ss2[1] + ss2[2] + ss2[3];
    float mu  = s * (1.0f / 128.0f);
    float var = s2 * (1.0f / 128.0f) - mu * mu;
    float t = (v - mu) * rsqrtf(var + 1e-5f) * gamma[d] + beta[d];
    g_h[gi * Dd + d] = 0.5f * t * (1.0f + erff(t * 0.70710678118654752f));
}

// ---------------------------------------------------------------------------
// S up-sweep stage A: one block per (batch, 8-leaf subtree). 14 loads/thread.
// Writes agg for levels 9,8,7 and raw S7 -> g_S7.
// Blocks 1024..1031: zero agg row of global node 0 per batch.
// ---------------------------------------------------------------------------
__global__ void s1a_kernel() {
    int bid = blockIdx.x;
    int d = threadIdx.x;
    if (bid >= 1024) {
        g_agg[((bid - 1024) * Nn) * Dd + d] = 0.f;
        return;
    }
    int b = bid >> 7;
    int s8 = bid & 127;
    int bN = b * Nn;

    float hv[8];
#pragma unroll
    for (int j = 0; j < 8; j++)
        hv[j] = g_h[(bN + LEAF + s8 * 8 + j) * Dd + d];

    // level 9 (nodes 512+4*s8+j), deg=2
    float S9[4];
#pragma unroll
    for (int j = 0; j < 4; j++) {
        S9[j] = hv[2*j] + hv[2*j+1];
        g_agg[(bN + 512 + 4*s8 + j) * Dd + d] = S9[j] * 0.5f;
    }
    // level 8 (nodes 256+2*s8+j), deg=6
    float S8[2];
#pragma unroll
    for (int j = 0; j < 2; j++) {
        float h0 = g_h[(bN + 512 + 4*s8 + 2*j) * Dd + d];
        float h1 = g_h[(bN + 512 + 4*s8 + 2*j + 1) * Dd + d];
        S8[j] = (h0 + S9[2*j]) + (h1 + S9[2*j+1]);
        g_agg[(bN + 256 + 2*s8 + j) * Dd + d] = S8[j] * (1.0f / 6.0f);
    }
    // level 7 (node 128+s8), deg=14
    {
        float h0 = g_h[(bN + 256 + 2*s8) * Dd + d];
        float h1 = g_h[(bN + 256 + 2*s8 + 1) * Dd + d];
        float S7 = (h0 + S8[0]) + (h1 + S8[1]);
        g_agg[(bN + 128 + s8) * Dd + d] = S7 * (1.0f / 14.0f);
        g_S7[(b * 128 + s8) * Dd + d] = S7;
    }
}

// ---------------------------------------------------------------------------
// S up-sweep stage B: one block per (batch, level-5 node). 10 loads/thread.
// Writes agg for levels 6,5 and raw S5 -> g_Stop.
// ---------------------------------------------------------------------------
__global__ void s1b_kernel() {
    int bid = blockIdx.x;
    int d = threadIdx.x;
    int b = bid >> 5;
    int s = bid & 31;
    int bN = b * Nn;

    // level 6 (nodes 64+2s+j), deg=30
    float S6[2];
#pragma unroll
    for (int j = 0; j < 2; j++) {
        float h0 = g_h[(bN + 128 + 4*s + 2*j) * Dd + d];
        float h1 = g_h[(bN + 128 + 4*s + 2*j + 1) * Dd + d];
        float s70 = g_S7[(b * 128 + 4*s + 2*j) * Dd + d];
        float s71 = g_S7[(b * 128 + 4*s + 2*j + 1) * Dd + d];
        S6[j] = (h0 + s70) + (h1 + s71);
        g_agg[(bN + 64 + 2*s + j) * Dd + d] = S6[j] * (1.0f / 30.0f);
    }
    // level 5 (node 32+s), deg=62
    {
        float h0 = g_h[(bN + 64 + 2*s) * Dd + d];
        float h1 = g_h[(bN + 64 + 2*s + 1) * Dd + d];
        float S5 = (h0 + S6[0]) + (h1 + S6[1]);
        g_agg[(bN + 32 + s) * Dd + d] = S5 * (1.0f / 62.0f);
        g_Stop[(b * 32 + s) * Dd + d] = S5;
    }
}

// ---------------------------------------------------------------------------
// Leaf gather aggregation (window traces). 256 threads = 8 gather groups.
// Segment bounds built by tid0 (<=16 serial iters), list expanded in parallel.
// ---------------------------------------------------------------------------
__global__ void aggleaf_kernel() {
    __shared__ __align__(16) float sbuf[8 * Dd];
    __shared__ __align__(16) int   slist[160];
    __shared__ int   segS[26], segP[26];
    __shared__ int   sNseg, sL;

    int bid = blockIdx.x;
    int tid = threadIdx.x;
    int g = tid >> 5, l = tid & 31;
    int b = bid >> 10;
    int local = LEAF + (bid & 1023);
    int bN = b * Nn;

    if (tid == 0) {
        int nseg = 0, tot = 0;
        int ni = local, cd = 10;
        bool stop = false;
        while (!stop) {
            int cs = (ni - 3) & ~1;
            stop = cs < (1 << cd);
            cs = max(cs, 1 << cd);
            segS[nseg] = cs; segP[nseg] = tot;
            tot += ni - cs + 1; nseg++;
            ni = (cs - 1) >> 1;
            cd--;
        }
        ni = local; cd = 10; stop = false;
        while (!stop) {
            int ce = ni + 3 + ((ni - 4) & 1);
            stop = ce >= (2 << cd);
            ce = min(ce, (2 << cd) - 1);
            segS[nseg] = ni; segP[nseg] = tot;
            tot += ce - ni + 1; nseg++;
            ni = (ce + 1) >> 1;
            cd--;
        }
        segP[nseg] = tot;
        sNseg = nseg; sL = tot;
    }
    __syncthreads();

    int L = sL;
    {
        int nseg = sNseg;
        for (int t = tid; t < L; t += 256) {
            int s = 0;
            while (s + 1 < nseg && segP[s + 1] <= t) s++;
            slist[t] = segS[s] + (t - segP[s]);
        }
    }
    __syncthreads();

    const float* __restrict__ hbase = &g_h[bN * Dd];
    float4 acc = make_float4(0.f, 0.f, 0.f, 0.f);
    int t = g;
    for (; t + 24 < L; t += 32) {
        int e0 = slist[t], e1 = slist[t + 8], e2 = slist[t + 16], e3 = slist[t + 24];
        float4 v0 = *(const float4*)&hbase[e0 * Dd + l * 4];
        float4 v1 = *(const float4*)&hbase[e1 * Dd + l * 4];
        float4 v2 = *(const float4*)&hbase[e2 * Dd + l * 4];
        float4 v3 = *(const float4*)&hbase[e3 * Dd + l * 4];
        acc.x += (v0.x + v1.x) + (v2.x + v3.x);
        acc.y += (v0.y + v1.y) + (v2.y + v3.y);
        acc.z += (v0.z + v1.z) + (v2.z + v3.z);
        acc.w += (v0.w + v1.w) + (v2.w + v3.w);
    }
    for (; t < L; t += 8) {
        int e0 = slist[t];
        float4 v0 = *(const float4*)&hbase[e0 * Dd + l * 4];
        acc.x += v0.x; acc.y += v0.y; acc.z += v0.z; acc.w += v0.w;
    }
    *(float4*)&sbuf[g * Dd + l * 4] = acc;
    __syncthreads();
    if (tid < Dd) {
        float v = ((sbuf[tid] + sbuf[Dd + tid]) + (sbuf[2*Dd + tid] + sbuf[3*Dd + tid]))
                + ((sbuf[4*Dd + tid] + sbuf[5*Dd + tid]) + (sbuf[6*Dd + tid] + sbuf[7*Dd + tid]));
        g_agg[(bN + local) * Dd + tid] = v * (1.0f / (float)L);
    }
}

// ---------------------------------------------------------------------------
// Mid nodes 1..31: gather descendants' h (levels lvl+1..5) + level-5 S rows.
// ---------------------------------------------------------------------------
__global__ void aggmid_kernel() {
    __shared__ __align__(16) float sbuf[4 * Dd];
    __shared__ __align__(16) int   slist[96];
    __shared__ int   sL;
    __shared__ float sInv;

    int w = blockIdx.x;
    int tid = threadIdx.x;
    int g = tid >> 5, l = tid & 31;
    int b = w / 31;
    int local = 1 + w % 31;
    int bN = b * Nn;

    if (tid == 0) {
        int lvl = 31 - __clz(local);
        int cnt = 0;
        for (int k = 1; k <= 5 - lvl; k++) {
            int s0 = local << k;
            for (int j = 0; j < (1 << k); j++) slist[cnt++] = s0 + j;
        }
        int s5 = local << (5 - lvl);
        for (int j = 0; j < (1 << (5 - lvl)); j++)
            slist[cnt++] = SFLAG | (s5 + j);
        sL = cnt;
        int deg = (1 << (11 - lvl)) - 2;
        sInv = 1.0f / (float)deg;
    }
    __syncthreads();

    int L = sL;
    const float* __restrict__ hbase = &g_h[bN * Dd];
    const float* __restrict__ sbase = &g_Stop[b * 32 * Dd];

    float4 acc = make_float4(0.f, 0.f, 0.f, 0.f);
    int t = g;
    for (; t + 12 < L; t += 16) {
        int e0 = slist[t], e1 = slist[t + 4], e2 = slist[t + 8], e3 = slist[t + 12];
        const float* r0 = (e0 & SFLAG) ? &sbase[((e0 & 0xFFFF) - 32) * Dd] : &hbase[e0 * Dd];
        const float* r1 = (e1 & SFLAG) ? &sbase[((e1 & 0xFFFF) - 32) * Dd] : &hbase[e1 * Dd];
        const float* r2 = (e2 & SFLAG) ? &sbase[((e2 & 0xFFFF) - 32) * Dd] : &hbase[e2 * Dd];
        const float* r3 = (e3 & SFLAG) ? &sbase[((e3 & 0xFFFF) - 32) * Dd] : &hbase[e3 * Dd];
        float4 v0 = *(const float4*)&r0[l * 4];
        float4 v1 = *(const float4*)&r1[l * 4];
        float4 v2 = *(const float4*)&r2[l * 4];
        float4 v3 = *(const float4*)&r3[l * 4];
        acc.x += (v0.x + v1.x) + (v2.x + v3.x);
        acc.y += (v0.y + v1.y) + (v2.y + v3.y);
        acc.z += (v0.z + v1.z) + (v2.z + v3.z);
        acc.w += (v0.w + v1.w) + (v2.w + v3.w);
    }
    for (; t < L; t += 4) {
        int e0 = slist[t];
        const float* r0 = (e0 & SFLAG) ? &sbase[((e0 & 0xFFFF) - 32) * Dd] : &hbase[e0 * Dd];
        float4 v0 = *(const float4*)&r0[l * 4];
        acc.x += v0.x; acc.y += v0.y; acc.z += v0.z; acc.w += v0.w;
    }
    *(float4*)&sbuf[g * Dd + l * 4] = acc;
    __syncthreads();
    float v = sbuf[tid] + sbuf[Dd + tid] + sbuf[2 * Dd + tid] + sbuf[3 * Dd + tid];
    g_agg[(bN + local) * Dd + tid] = v * sInv;
}

// ---------------------------------------------------------------------------
// x += agg @ W1 + bias + h @ W2, f32x2 packed FMA, register tile prefetch.
// BM=64, BN=128 (full), BK=32, 128 threads, 8x8 micro-tile.
// FUSE: epilogue computes next layer's h = gelu(LN(x_new)) into g_h.
// ---------------------------------------------------------------------------
template<bool FUSE>
__global__ void __launch_bounds__(128) gemm_kernel(
    const float* __restrict__ W1, const float* __restrict__ W2,
    const float* __restrict__ bias,
    const float* __restrict__ gamma, const float* __restrict__ beta,
    float* __restrict__ X)
{
    __shared__ __align__(16) unsigned long long As2[32][64];   // 16 KB, (a,a) pairs
    __shared__ __align__(16) float Bs[32][128];                // 16 KB
    const int bm = blockIdx.x * 64;
    const int tid = threadIdx.x;
    const int trow = tid >> 4;   // 0..7
    const int tcol = tid & 15;   // 0..15
    const int tm = trow * 8;
    const int tn = tcol * 8;

    const int m = tid >> 1, half = tid & 1, kb = half * 16;
    const int kkB = tid >> 2, qB = tid & 3;

    unsigned long long acc[8][4];
#pragma unroll
    for (int i = 0; i < 8; i++)
#pragma unroll
        for (int j = 0; j < 4; j++) acc[i][j] = 0ull;

    float4 aR[4], bR[8];
    // preload tile 0 (pass 0 = g_agg/W1, k0 = 0)
    {
        const float* ap = &g_agg[(bm + m) * Dd + half * 16];
#pragma unroll
        for (int j = 0; j < 4; j++) aR[j] = *(const float4*)(ap + j * 4);
        const float* wp = &W1[kkB * Dd + qB * 32];
#pragma unroll
        for (int j = 0; j < 8; j++) bR[j] = *(const float4*)(wp + j * 4);
    }

#pragma unroll
    for (int it = 0; it < 8; it++) {
        // store prefetched tile to smem
#pragma unroll
        for (int j = 0; j < 4; j++) {
            As2[kb + j*4 + 0][m] = pack2(aR[j].x, aR[j].x);
            As2[kb + j*4 + 1][m] = pack2(aR[j].y, aR[j].y);
            As2[kb + j*4 + 2][m] = pack2(aR[j].z, aR[j].z);
            As2[kb + j*4 + 3][m] = pack2(aR[j].w, aR[j].w);
        }
#pragma unroll
        for (int j = 0; j < 8; j++)
            *(float4*)&Bs[kkB][qB * 32 + j * 4] = bR[j];
        __syncthreads();

        // prefetch next tile (LDG latency hidden by compute below)
        if (it < 7) {
            const int nit = it + 1;
            const float* Ap = (nit >= 4) ? (const float*)g_h : (const float*)g_agg;
            const float* Wp = (nit >= 4) ? W2 : W1;
            const int k0 = (nit & 3) * 32;
            const float* ap = &Ap[(bm + m) * Dd + k0 + half * 16];
#pragma unroll
            for (int j = 0; j < 4; j++) aR[j] = *(const float4*)(ap + j * 4);
            const float* wp = &Wp[(k0 + kkB) * Dd + qB * 32];
#pragma unroll
            for (int j = 0; j < 8; j++) bR[j] = *(const float4*)(wp + j * 4);
        }

#pragma unroll
        for (int kk = 0; kk < 32; kk++) {
            ulonglong2 a01 = *(const ulonglong2*)&As2[kk][tm];
            ulonglong2 a23 = *(const ulonglong2*)&As2[kk][tm + 2];
            ulonglong2 a45 = *(const ulonglong2*)&As2[kk][tm + 4];
            ulonglong2 a67 = *(const ulonglong2*)&As2[kk][tm + 6];
            ulonglong2 b01 = *(const ulonglong2*)&Bs[kk][tn];
            ulonglong2 b23 = *(const ulonglong2*)&Bs[kk][tn + 4];
            unsigned long long ap[8] = {a01.x, a01.y, a23.x, a23.y,
                                        a45.x, a45.y, a67.x, a67.y};
            unsigned long long bp[4] = {b01.x, b01.y, b23.x, b23.y};
#pragma unroll
            for (int i = 0; i < 8; i++) {
                ffma2(acc[i][0], ap[i], bp[0]);
                ffma2(acc[i][1], ap[i], bp[1]);
                ffma2(acc[i][2], ap[i], bp[2]);
                ffma2(acc[i][3], ap[i], bp[3]);
            }
        }
        __syncthreads();
    }

    // Epilogue
    float bb[8], gg[8], be[8];
#pragma unroll
    for (int j = 0; j < 8; j++) bb[j] = bias[tn + j];
    if (FUSE) {
#pragma unroll
        for (int j = 0; j < 8; j++) { gg[j] = gamma[tn + j]; be[j] = beta[tn + j]; }
    }
#pragma unroll
    for (int i = 0; i < 8; i++) {
        int row = bm + tm + i;
        float4 x0 = *(const float4*)&X[row * Dd + tn];
        float4 x1 = *(const float4*)&X[row * Dd + tn + 4];
        float xv[8] = {x0.x, x0.y, x0.z, x0.w, x1.x, x1.y, x1.z, x1.w};
#pragma unroll
        for (int j = 0; j < 4; j++) {
            float lo, hi;
            unpack2(acc[i][j], lo, hi);
            xv[2*j]   += lo + bb[2*j];
            xv[2*j+1] += hi + bb[2*j+1];
        }
        x0 = make_float4(xv[0], xv[1], xv[2], xv[3]);
        x1 = make_float4(xv[4], xv[5], xv[6], xv[7]);
        *(float4*)&X[row * Dd + tn]     = x0;
        *(float4*)&X[row * Dd + tn + 4] = x1;
        if (FUSE) {
            float s = 0.f, s2 = 0.f;
#pragma unroll
            for (int j = 0; j < 8; j++) { s += xv[j]; s2 += xv[j] * xv[j]; }
#pragma unroll
            for (int o = 1; o <= 8; o <<= 1) {
                s  += __shfl_xor_sync(0xffffffffu, s, o);
                s2 += __shfl_xor_sync(0xffffffffu, s2, o);
            }
            float mu  = s * (1.0f / 128.0f);
            float var = s2 * (1.0f / 128.0f) - mu * mu;
            float rs  = rsqrtf(var + 1e-5f);
            float hv[8];
#pragma unroll
            for (int j = 0; j < 8; j++) {
                float t = (xv[j] - mu) * rs * gg[j] + be[j];
                hv[j] = 0.5f * t * (1.0f + erff(t * 0.70710678118654752f));
            }
            *(float4*)&g_h[row * Dd + tn]     = make_float4(hv[0], hv[1], hv[2], hv[3]);
            *(float4*)&g_h[row * Dd + tn + 4] = make_float4(hv[4], hv[5], hv[6], hv[7]);
        }
    }
}

// ---------------------------------------------------------------------------
extern "C" void kernel_launch(void* const* d_in, const int* in_sizes, int n_in,
                              void* d_out, int out_size) {
    const float* elements = (const float*)d_in[0];
    const float* ln_gamma = (const float*)d_in[1];
    const float* ln_beta  = (const float*)d_in[2];
    const float* w_nei    = (const float*)d_in[3];
    const float* b_nei    = (const float*)d_in[4];
    const float* w_root   = (const float*)d_in[5];
    float* x = (float*)d_out;

    tree1_kernel<<<Bb * 32, Dd>>>(elements);                       // 1
    tree2_kernel<<<Bb, Dd>>>();                                    // 2
    encx_kernel<<<BN, Dd>>>(x, ln_gamma, ln_beta);                 // 3

    // layer 0 (gemm fuses LN+GELU for layer 1 into its epilogue)
    aggleaf_kernel<<<8192, 256>>>();                               // 4 (profiled)
    s1a_kernel<<<Bb * 128 + 8, Dd>>>();                            // 5
    s1b_kernel<<<Bb * 32, Dd>>>();                                 // 6
    aggmid_kernel<<<Bb * 31, Dd>>>();                              // 7
    gemm_kernel<true><<<BN / 64, 128>>>(w_nei, w_root, b_nei,
                                        ln_gamma + Dd, ln_beta + Dd, x);

    // layer 1 (final — no fused LN)
    aggleaf_kernel<<<8192, 256>>>();
    s1a_kernel<<<Bb * 128 + 8, Dd>>>();
    s1b_kernel<<<Bb * 32, Dd>>>();
    aggmid_kernel<<<Bb * 31, Dd>>>();
    gemm_kernel<false><<<BN / 64, 128>>>(w_nei + Dd * Dd, w_root + Dd * Dd,
                                         b_nei + Dd, nullptr, nullptr, x);
}

// round 8
// speedup vs baseline: 1.1755x; 1.1755x over previous
#include <cuda_runtime.h>
#include <math.h>

#define Bb   8
#define LEAF 1024
#define Nn   2048
#define Dd   128
#define BN   (Bb * Nn)      // 16384
#define HEAVY_PER_B 15      // locals 1..15 have deg > 128
#define HCHUNKS 16          // 16 chunks x 128 edges covers deg <= 2046
#define HEAVY_W (Bb * HEAVY_PER_B * HCHUNKS)   // 1920

// Scratch (allocation-free rule: device globals)
__device__ float g_nf  [BN * Dd];          // raw node features (tree means)
__device__ float g_h   [BN * Dd];          // gelu(LN(x))
__device__ float g_agg [BN * Dd];          // mean aggregation
__device__ float g_part[HEAVY_W * Dd];     // heavy-node partial sums
__device__ int   g_off [BN + 1];           // CSR offsets into edge list

// ---------------------------------------------------------------------------
// f32x2 packed helpers (SASS FFMA2 — PTX-only)
// ---------------------------------------------------------------------------
__device__ __forceinline__ unsigned long long pack2(float lo, float hi) {
    unsigned long long r;
    asm("mov.b64 %0, {%1, %2};" : "=l"(r) : "f"(lo), "f"(hi));
    return r;
}
__device__ __forceinline__ void unpack2(unsigned long long v, float& lo, float& hi) {
    asm("mov.b64 {%0, %1}, %2;" : "=f"(lo), "=f"(hi) : "l"(v));
}
__device__ __forceinline__ void ffma2(unsigned long long& d,
                                      unsigned long long a,
                                      unsigned long long b) {
    asm("fma.rn.f32x2 %0, %1, %2, %0;" : "+l"(d) : "l"(a), "l"(b));
}

// ---------------------------------------------------------------------------
// Tree build: pairwise mean up-sweep. Each thread owns one feature dim d.
// ---------------------------------------------------------------------------
__device__ __forceinline__ void reduce_store(const float v32[32], int bN, int base, int off, int d) {
    float v16[16];
#pragma unroll
    for (int j = 0; j < 16; j++) {
        v16[j] = 0.5f * (v32[2*j] + v32[2*j+1]);
        g_nf[(bN + (base >> 1) + (off >> 1) + j) * Dd + d] = v16[j];
    }
    float v8[8];
#pragma unroll
    for (int j = 0; j < 8; j++) {
        v8[j] = 0.5f * (v16[2*j] + v16[2*j+1]);
        g_nf[(bN + (base >> 2) + (off >> 2) + j) * Dd + d] = v8[j];
    }
    float v4[4];
#pragma unroll
    for (int j = 0; j < 4; j++) {
        v4[j] = 0.5f * (v8[2*j] + v8[2*j+1]);
        g_nf[(bN + (base >> 3) + (off >> 3) + j) * Dd + d] = v4[j];
    }
    float v2[2];
#pragma unroll
    for (int j = 0; j < 2; j++) {
        v2[j] = 0.5f * (v4[2*j] + v4[2*j+1]);
        g_nf[(bN + (base >> 4) + (off >> 4) + j) * Dd + d] = v2[j];
    }
    float v1 = 0.5f * (v2[0] + v2[1]);
    g_nf[(bN + (base >> 5) + (off >> 5)) * Dd + d] = v1;
}

__global__ void tree1_kernel(const float* __restrict__ elements) {
    int b = blockIdx.x >> 5;
    int s = blockIdx.x & 31;
    int d = threadIdx.x;
    int bN = b * Nn;
    float v32[32];
#pragma unroll
    for (int j = 0; j < 32; j++) {
        float v = elements[(b * LEAF + s * 32 + j) * Dd + d];
        v32[j] = v;
        g_nf[(bN + LEAF + s * 32 + j) * Dd + d] = v;
    }
    reduce_store(v32, bN, 1024, s * 32, d);
}

// ---------------------------------------------------------------------------
// Fused: blocks 0..7 finish the tree (nodes 1..31 + global node 0);
// blocks 8.. compute CSR offsets edge-parallel (dst globally nondecreasing).
// ---------------------------------------------------------------------------
__global__ void tree2off_kernel(const int* __restrict__ dst, int E) {
    if (blockIdx.x < 8) {
        int d = threadIdx.x;
        if (d < Dd) {
            int b = blockIdx.x;
            int bN = b * Nn;
            float v32[32];
#pragma unroll
            for (int j = 0; j < 32; j++)
                v32[j] = g_nf[(bN + 32 + j) * Dd + d];
            reduce_store(v32, bN, 32, 0, d);
            g_nf[bN * Dd + d] = -1.0f;  // global node 0
        }
        return;
    }
    int e = (blockIdx.x - 8) * 256 + threadIdx.x;
    if (e >= E) return;
    int d1 = dst[e];
    int d0 = (e == 0) ? -1 : dst[e - 1];
    for (int i = d0 + 1; i <= d1; i++) g_off[i] = e;
    if (e == E - 1)
        for (int i = d1 + 1; i <= BN; i++) g_off[i] = E;
}

// ---------------------------------------------------------------------------
// x = nf + positional encoding; fused LN + exact GELU -> g_h (layer 0 input)
// ---------------------------------------------------------------------------
__global__ void encx_kernel(float* __restrict__ x,
                            const float* __restrict__ gamma,
                            const float* __restrict__ beta) {
    int gi = blockIdx.x;
    int node = gi & (Nn - 1);
    int d = threadIdx.x;
    float pos;
    if (node == 0) {
        pos = (d < 64) ? -0.5f : -1.0f;
    } else {
        int vp = 31 - __clz(node);
        pos = (d < 64) ? (float)(node - (1 << vp)) : (float)vp;
    }
    int dd = d & 63;
    int k = dd >> 1;
    float inv = expf(-0.28782313662425574f * (float)k);   // exp(-k*ln(1e4)/32)
    float ang = pos * inv;
    float e = (dd & 1) ? cosf(ang) : sinf(ang);
    float v = g_nf[gi * Dd + d] + e;
    x[gi * Dd + d] = v;

    float s = v, s2 = v * v;
#pragma unroll
    for (int o = 16; o; o >>= 1) {
        s  += __shfl_xor_sync(0xffffffffu, s, o);
        s2 += __shfl_xor_sync(0xffffffffu, s2, o);
    }
    __shared__ float ss[4], ss2[4];
    int w = d >> 5, lane = d & 31;
    if (lane == 0) { ss[w] = s; ss2[w] = s2; }
    __syncthreads();
    s  = ss[0] + ss[1] + ss[2] + ss[3];
    s2 = ss2[0] + ss2[1] + ss2[2] + ss2[3];
    float mu  = s * (1.0f / 128.0f);
    float var = s2 * (1.0f / 128.0f) - mu * mu;
    float t = (v - mu) * rsqrtf(var + 1e-5f) * gamma[d] + beta[d];
    g_h[gi * Dd + d] = 0.5f * t * (1.0f + erff(t * 0.70710678118654752f));
}

// ---------------------------------------------------------------------------
// Aggregation: float4 gather, 4 edge-groups per block, 4 rows in flight.
//   blocks [0, BN):       one node each (heavy locals 1..15 skipped)
//   blocks [BN, BN+1920): heavy-node 128-edge chunks -> g_part
// ---------------------------------------------------------------------------
__global__ void agg_kernel(const int* __restrict__ src) {
    __shared__ __align__(16) float sbuf[4 * Dd];
    int bid = blockIdx.x;
    int tid = threadIdx.x;
    int g = tid >> 5, l = tid & 31;
    int s, e;
    float scale;
    float* out;
    if (bid < BN) {
        int i = bid;
        int local = i & (Nn - 1);
        if (local >= 1 && local <= HEAVY_PER_B) return;   // heavy path handles
        s = g_off[i];
        e = g_off[i + 1];
        int deg = e - s;
        scale = 1.0f / (float)(deg > 0 ? deg : 1);
        out = &g_agg[i * Dd];
    } else {
        int w = bid - BN;
        int b = w / (HEAVY_PER_B * HCHUNKS);
        int r = w % (HEAVY_PER_B * HCHUNKS);
        int local = 1 + (r >> 4);
        int c = r & 15;
        int i = b * Nn + local;
        int s0 = g_off[i], e0 = g_off[i + 1];
        s = s0 + c * 128;
        e = min(e0, s + 128);
        if (e < s) e = s;
        scale = 1.0f;
        out = &g_part[w * Dd];
    }
    float4 acc = make_float4(0.f, 0.f, 0.f, 0.f);
    int t = s + g;
    for (; t + 12 < e; t += 16) {
        int i0 = __ldg(&src[t]);
        int i1 = __ldg(&src[t + 4]);
        int i2 = __ldg(&src[t + 8]);
        int i3 = __ldg(&src[t + 12]);
        float4 v0 = *(const float4*)&g_h[i0 * Dd + l * 4];
        float4 v1 = *(const float4*)&g_h[i1 * Dd + l * 4];
        float4 v2 = *(const float4*)&g_h[i2 * Dd + l * 4];
        float4 v3 = *(const float4*)&g_h[i3 * Dd + l * 4];
        acc.x += (v0.x + v1.x) + (v2.x + v3.x);
        acc.y += (v0.y + v1.y) + (v2.y + v3.y);
        acc.z += (v0.z + v1.z) + (v2.z + v3.z);
        acc.w += (v0.w + v1.w) + (v2.w + v3.w);
    }
    for (; t < e; t += 4) {
        int i0 = __ldg(&src[t]);
        float4 v0 = *(const float4*)&g_h[i0 * Dd + l * 4];
        acc.x += v0.x; acc.y += v0.y; acc.z += v0.z; acc.w += v0.w;
    }
    *(float4*)&sbuf[g * Dd + l * 4] = acc;
    __syncthreads();
    float v = sbuf[tid] + sbuf[Dd + tid] + sbuf[2 * Dd + tid] + sbuf[3 * Dd + tid];
    out[tid] = v * scale;
}

// Deterministic fixup: sum the 16 partials of each heavy node in fixed order.
__global__ void aggfix_kernel() {
    int b = blockIdx.x / HEAVY_PER_B;
    int r = blockIdx.x % HEAVY_PER_B;
    int local = r + 1;
    int i = b * Nn + local;
    int t = threadIdx.x;
    float sum = 0.f;
#pragma unroll
    for (int c = 0; c < HCHUNKS; c++)
        sum += g_part[((b * HEAVY_PER_B + r) * HCHUNKS + c) * Dd + t];
    int deg = g_off[i + 1] - g_off[i];
    g_agg[i * Dd + t] = sum / (float)(deg > 0 ? deg : 1);
}

// ---------------------------------------------------------------------------
// x += agg @ W1 + bias + h @ W2, f32x2 packed FMA with zero in-loop packing:
// A tile stored as duplicated (a,a) 8B pairs; B pairs loaded via ulonglong2.
// BM=64, BN=128 (full), BK=32, 128 threads, 8x8 micro-tile. No prefetch
// (r7 showed prefetch register pressure regresses).
// FUSE: epilogue computes next layer's h = gelu(LN(x_new)) into g_h.
// ---------------------------------------------------------------------------
template<bool FUSE>
__global__ void __launch_bounds__(128) gemm_kernel(
    const float* __restrict__ W1, const float* __restrict__ W2,
    const float* __restrict__ bias,
    const float* __restrict__ gamma, const float* __restrict__ beta,
    float* __restrict__ X)
{
    __shared__ __align__(16) unsigned long long As2[32][64];   // 16 KB, (a,a) pairs
    __shared__ __align__(16) float Bs[32][128];                // 16 KB
    const int bm = blockIdx.x * 64;
    const int tid = threadIdx.x;
    const int trow = tid >> 4;   // 0..7
    const int tcol = tid & 15;   // 0..15
    const int tm = trow * 8;
    const int tn = tcol * 8;

    unsigned long long acc[8][4];
#pragma unroll
    for (int i = 0; i < 8; i++)
#pragma unroll
        for (int j = 0; j < 4; j++) acc[i][j] = 0ull;

#pragma unroll
    for (int pass = 0; pass < 2; pass++) {
        const float* A = pass ? g_h : g_agg;
        const float* W = pass ? W2 : W1;
#pragma unroll
        for (int k0 = 0; k0 < Dd; k0 += 32) {
            {
                int m = tid >> 1, half = tid & 1;
                const float* ap = &A[(bm + m) * Dd + k0 + half * 16];
                int kb = half * 16;
#pragma unroll
                for (int j = 0; j < 4; j++) {
                    float4 v = *(const float4*)(ap + j * 4);
                    As2[kb + j*4 + 0][m] = pack2(v.x, v.x);
                    As2[kb + j*4 + 1][m] = pack2(v.y, v.y);
                    As2[kb + j*4 + 2][m] = pack2(v.z, v.z);
                    As2[kb + j*4 + 3][m] = pack2(v.w, v.w);
                }
            }
            {
                int kk = tid >> 2, q = tid & 3;
                const float* wp = &W[(k0 + kk) * Dd + q * 32];
#pragma unroll
                for (int j = 0; j < 8; j++)
                    *(float4*)&Bs[kk][q * 32 + j * 4] = *(const float4*)(wp + j * 4);
            }
            __syncthreads();
#pragma unroll
            for (int kk = 0; kk < 32; kk++) {
                ulonglong2 a01 = *(const ulonglong2*)&As2[kk][tm];
                ulonglong2 a23 = *(const ulonglong2*)&As2[kk][tm + 2];
                ulonglong2 a45 = *(const ulonglong2*)&As2[kk][tm + 4];
                ulonglong2 a67 = *(const ulonglong2*)&As2[kk][tm + 6];
                ulonglong2 b01 = *(const ulonglong2*)&Bs[kk][tn];
                ulonglong2 b23 = *(const ulonglong2*)&Bs[kk][tn + 4];
                unsigned long long ap[8] = {a01.x, a01.y, a23.x, a23.y,
                                            a45.x, a45.y, a67.x, a67.y};
                unsigned long long bp[4] = {b01.x, b01.y, b23.x, b23.y};
#pragma unroll
                for (int i = 0; i < 8; i++) {
                    ffma2(acc[i][0], ap[i], bp[0]);
                    ffma2(acc[i][1], ap[i], bp[1]);
                    ffma2(acc[i][2], ap[i], bp[2]);
                    ffma2(acc[i][3], ap[i], bp[3]);
                }
            }
            __syncthreads();
        }
    }

    // Epilogue
    float bb[8], gg[8], be[8];
#pragma unroll
    for (int j = 0; j < 8; j++) bb[j] = bias[tn + j];
    if (FUSE) {
#pragma unroll
        for (int j = 0; j < 8; j++) { gg[j] = gamma[tn + j]; be[j] = beta[tn + j]; }
    }
#pragma unroll
    for (int i = 0; i < 8; i++) {
        int row = bm + tm + i;
        float4 x0 = *(const float4*)&X[row * Dd + tn];
        float4 x1 = *(const float4*)&X[row * Dd + tn + 4];
        float xv[8] = {x0.x, x0.y, x0.z, x0.w, x1.x, x1.y, x1.z, x1.w};
#pragma unroll
        for (int j = 0; j < 4; j++) {
            float lo, hi;
            unpack2(acc[i][j], lo, hi);
            xv[2*j]   += lo + bb[2*j];
            xv[2*j+1] += hi + bb[2*j+1];
        }
        x0 = make_float4(xv[0], xv[1], xv[2], xv[3]);
        x1 = make_float4(xv[4], xv[5], xv[6], xv[7]);
        *(float4*)&X[row * Dd + tn]     = x0;
        *(float4*)&X[row * Dd + tn + 4] = x1;
        if (FUSE) {
            float s = 0.f, s2 = 0.f;
#pragma unroll
            for (int j = 0; j < 8; j++) { s += xv[j]; s2 += xv[j] * xv[j]; }
#pragma unroll
            for (int o = 1; o <= 8; o <<= 1) {
                s  += __shfl_xor_sync(0xffffffffu, s, o);
                s2 += __shfl_xor_sync(0xffffffffu, s2, o);
            }
            float mu  = s * (1.0f / 128.0f);
            float var = s2 * (1.0f / 128.0f) - mu * mu;
            float rs  = rsqrtf(var + 1e-5f);
            float hv[8];
#pragma unroll
            for (int j = 0; j < 8; j++) {
                float t = (xv[j] - mu) * rs * gg[j] + be[j];
                hv[j] = 0.5f * t * (1.0f + erff(t * 0.70710678118654752f));
            }
            *(float4*)&g_h[row * Dd + tn]     = make_float4(hv[0], hv[1], hv[2], hv[3]);
            *(float4*)&g_h[row * Dd + tn + 4] = make_float4(hv[4], hv[5], hv[6], hv[7]);
        }
    }
}

// ---------------------------------------------------------------------------
extern "C" void kernel_launch(void* const* d_in, const int* in_sizes, int n_in,
                              void* d_out, int out_size) {
    const float* elements = (const float*)d_in[0];
    const float* ln_gamma = (const float*)d_in[1];
    const float* ln_beta  = (const float*)d_in[2];
    const float* w_nei    = (const float*)d_in[3];
    const float* b_nei    = (const float*)d_in[4];
    const float* w_root   = (const float*)d_in[5];
    const int*   edges    = (const int*)d_in[6];
    float* x = (float*)d_out;

    int E = in_sizes[6] / 2;
    const int* src = edges;
    const int* dst = edges + E;

    tree1_kernel<<<Bb * 32, Dd>>>(elements);                        // 1
    tree2off_kernel<<<8 + (E + 255) / 256, 256>>>(dst, E);          // 2
    encx_kernel<<<BN, Dd>>>(x, ln_gamma, ln_beta);                  // 3

    // layer 0 (gemm fuses LN+GELU for layer 1 into its epilogue)
    agg_kernel<<<BN + HEAVY_W, Dd>>>(src);                          // 4 (profiled)
    aggfix_kernel<<<Bb * HEAVY_PER_B, Dd>>>();                      // 5
    gemm_kernel<true><<<BN / 64, 128>>>(w_nei, w_root, b_nei,
                                        ln_gamma + Dd, ln_beta + Dd, x);

    // layer 1 (final — no fused LN)
    agg_kernel<<<BN + HEAVY_W, Dd>>>(src);
    aggfix_kernel<<<Bb * HEAVY_PER_B, Dd>>>();
    gemm_kernel<false><<<BN / 64, 128>>>(w_nei + Dd * Dd, w_root + Dd * Dd,
                                         b_nei + Dd, nullptr, nullptr, x);
}